// round 1
// baseline (speedup 1.0000x reference)
#include <cuda_runtime.h>

#define NB 32
#define NC 512
#define NL 512
#define NH 8
#define NDK 64

// Scratch (device globals: no allocations allowed in kernel_launch)
__device__ float g_t[NB * NC * NL];      // dwconv output (reused q/k/v)
__device__ float g_q[NB * NC * NL];
__device__ float g_k[NB * NC * NL];
__device__ float g_v[NB * NC * NL];
__device__ float g_o[NB * NC * NL];      // attention output, (b, c=h*64+d, i)
__device__ float g_post[NC * NL];        // pos_bias transposed to (C, L)

// ---------------------------------------------------------------------------
// pos_bias (L, C) -> posT (C, L), so dwconv reads it coalesced
// ---------------------------------------------------------------------------
__global__ void transpose_pos_kernel(const float* __restrict__ pos,
                                     float* __restrict__ posT) {
    __shared__ float tile[32][33];
    const int c0 = blockIdx.x * 32;
    const int l0 = blockIdx.y * 32;
    const int tx = threadIdx.x;   // 32
    const int ty = threadIdx.y;   // 8
#pragma unroll
    for (int r = 0; r < 4; r++)
        tile[ty + r * 8][tx] = pos[(size_t)(l0 + ty + r * 8) * NC + c0 + tx];
    __syncthreads();
#pragma unroll
    for (int r = 0; r < 4; r++)
        posT[(size_t)(c0 + ty + r * 8) * NL + l0 + tx] = tile[tx][ty + r * 8];
}

// ---------------------------------------------------------------------------
// depthwise conv1d (K=7, pad=3) + optional pos-bias add. One block = (c, b).
// ---------------------------------------------------------------------------
__global__ __launch_bounds__(512) void dwconv_kernel(
    const float* __restrict__ x, const float* __restrict__ posT,
    const float* __restrict__ w, const float* __restrict__ bias,
    float* __restrict__ y, int add_pos) {
    const int c = blockIdx.x;
    const int b = blockIdx.y;
    const int l = threadIdx.x;
    __shared__ float xs[NL + 6];
    float v = x[((size_t)b * NC + c) * NL + l];
    if (add_pos) v += posT[(size_t)c * NL + l];
    xs[l + 3] = v;
    if (l < 3) { xs[l] = 0.f; xs[NL + 3 + l] = 0.f; }
    __syncthreads();
    float acc = bias[c];
#pragma unroll
    for (int t = 0; t < 7; t++) acc += xs[l + t] * w[c * 7 + t];
    y[((size_t)b * NC + c) * NL + l] = acc;
}

// ---------------------------------------------------------------------------
// GEMM NN: Y[z,m,n] = sum_k A[m,k] * B[z,k,n] + bias[m]
// (pointwise conv: m=o, k=c, n=l). BM=128, BN=64, BK=16, 256 thr, 8x4 microtile
// ---------------------------------------------------------------------------
__global__ __launch_bounds__(256) void gemm_nn_kernel(
    const float* __restrict__ A, const float* __restrict__ Bm,
    const float* __restrict__ bias, float* __restrict__ Y) {
    __shared__ float As[16][128];
    __shared__ float Bs[16][64];
    const int tid = threadIdx.x;
    const int tx = tid & 15;   // n
    const int ty = tid >> 4;   // m
    const int m0 = blockIdx.y * 128;
    const int n0 = blockIdx.x * 64;
    const float* Bb = Bm + (size_t)blockIdx.z * (512 * 512);
    float* Yb = Y + (size_t)blockIdx.z * (512 * 512);

    const int a_m = tid >> 1;          // 0..127
    const int a_k = (tid & 1) * 8;     // 0 or 8
    const int b_k = tid >> 4;          // 0..15
    const int b_n = (tid & 15) * 4;    // 0..60

    float acc[8][4];
#pragma unroll
    for (int i = 0; i < 8; i++)
#pragma unroll
        for (int j = 0; j < 4; j++) acc[i][j] = 0.f;

    for (int k0 = 0; k0 < 512; k0 += 16) {
        float4 a0 = *(const float4*)&A[(size_t)(m0 + a_m) * 512 + k0 + a_k];
        float4 a1 = *(const float4*)&A[(size_t)(m0 + a_m) * 512 + k0 + a_k + 4];
        float4 b0 = *(const float4*)&Bb[(size_t)(k0 + b_k) * 512 + n0 + b_n];
        __syncthreads();
        As[a_k + 0][a_m] = a0.x; As[a_k + 1][a_m] = a0.y;
        As[a_k + 2][a_m] = a0.z; As[a_k + 3][a_m] = a0.w;
        As[a_k + 4][a_m] = a1.x; As[a_k + 5][a_m] = a1.y;
        As[a_k + 6][a_m] = a1.z; As[a_k + 7][a_m] = a1.w;
        *(float4*)&Bs[b_k][b_n] = b0;
        __syncthreads();
#pragma unroll
        for (int k = 0; k < 16; k++) {
            float4 av0 = *(const float4*)&As[k][ty * 8];
            float4 av1 = *(const float4*)&As[k][ty * 8 + 4];
            float4 bv = *(const float4*)&Bs[k][tx * 4];
            float am[8] = {av0.x, av0.y, av0.z, av0.w, av1.x, av1.y, av1.z, av1.w};
            float bn_[4] = {bv.x, bv.y, bv.z, bv.w};
#pragma unroll
            for (int i = 0; i < 8; i++)
#pragma unroll
                for (int j = 0; j < 4; j++) acc[i][j] += am[i] * bn_[j];
        }
    }
#pragma unroll
    for (int i = 0; i < 8; i++) {
        const int m = m0 + ty * 8 + i;
        const float bv = bias[m];
        float4 o;
        o.x = acc[i][0] + bv; o.y = acc[i][1] + bv;
        o.z = acc[i][2] + bv; o.w = acc[i][3] + bv;
        *(float4*)&Yb[(size_t)m * 512 + n0 + tx * 4] = o;
    }
}

// ---------------------------------------------------------------------------
// GEMM NT: Y[z,m,n] = sum_k A[z,m,k] * W[n,k] + bias[n]
// (final proj: m = c index of attn-out, k = seq i, n = o)
// ---------------------------------------------------------------------------
__global__ __launch_bounds__(256) void gemm_nt_kernel(
    const float* __restrict__ Am, const float* __restrict__ W,
    const float* __restrict__ bias, float* __restrict__ Y) {
    __shared__ float As[16][128];
    __shared__ float Bs[16][64];
    const int tid = threadIdx.x;
    const int tx = tid & 15;
    const int ty = tid >> 4;
    const int m0 = blockIdx.y * 128;
    const int n0 = blockIdx.x * 64;
    const float* Ab = Am + (size_t)blockIdx.z * (512 * 512);
    float* Yb = Y + (size_t)blockIdx.z * (512 * 512);

    const int a_m = tid >> 1;
    const int a_k = (tid & 1) * 8;
    const int b_n = tid >> 2;          // 0..63
    const int b_k = (tid & 3) * 4;     // 0,4,8,12

    float acc[8][4];
#pragma unroll
    for (int i = 0; i < 8; i++)
#pragma unroll
        for (int j = 0; j < 4; j++) acc[i][j] = 0.f;

    for (int k0 = 0; k0 < 512; k0 += 16) {
        float4 a0 = *(const float4*)&Ab[(size_t)(m0 + a_m) * 512 + k0 + a_k];
        float4 a1 = *(const float4*)&Ab[(size_t)(m0 + a_m) * 512 + k0 + a_k + 4];
        float4 b0 = *(const float4*)&W[(size_t)(n0 + b_n) * 512 + k0 + b_k];
        __syncthreads();
        As[a_k + 0][a_m] = a0.x; As[a_k + 1][a_m] = a0.y;
        As[a_k + 2][a_m] = a0.z; As[a_k + 3][a_m] = a0.w;
        As[a_k + 4][a_m] = a1.x; As[a_k + 5][a_m] = a1.y;
        As[a_k + 6][a_m] = a1.z; As[a_k + 7][a_m] = a1.w;
        Bs[b_k + 0][b_n] = b0.x; Bs[b_k + 1][b_n] = b0.y;
        Bs[b_k + 2][b_n] = b0.z; Bs[b_k + 3][b_n] = b0.w;
        __syncthreads();
#pragma unroll
        for (int k = 0; k < 16; k++) {
            float4 av0 = *(const float4*)&As[k][ty * 8];
            float4 av1 = *(const float4*)&As[k][ty * 8 + 4];
            float4 bv = *(const float4*)&Bs[k][tx * 4];
            float am[8] = {av0.x, av0.y, av0.z, av0.w, av1.x, av1.y, av1.z, av1.w};
            float bn_[4] = {bv.x, bv.y, bv.z, bv.w};
#pragma unroll
            for (int i = 0; i < 8; i++)
#pragma unroll
                for (int j = 0; j < 4; j++) acc[i][j] += am[i] * bn_[j];
        }
    }
    float4 bb = *(const float4*)&bias[n0 + tx * 4];
#pragma unroll
    for (int i = 0; i < 8; i++) {
        const int m = m0 + ty * 8 + i;
        float4 o;
        o.x = acc[i][0] + bb.x; o.y = acc[i][1] + bb.y;
        o.z = acc[i][2] + bb.z; o.w = acc[i][3] + bb.w;
        *(float4*)&Yb[(size_t)m * 512 + n0 + tx * 4] = o;
    }
}

// ---------------------------------------------------------------------------
// Flash-style attention. Q,K,V stored as (b, c=h*64+d, l). One block handles
// (b, h, 64-row i-tile). Online softmax over 8 j-tiles of 64.
// S[i,j] = sum_d Q[d,i]*K[d,j] * 0.125 ; O[d,i] = softmax(S) @ V[d,:]
// Dynamic smem: Qs[64][64] | KP[64][68] (K tile, then reused for P) | Vs[64][68]
// ---------------------------------------------------------------------------
__global__ __launch_bounds__(256) void attn_kernel(
    const float* __restrict__ Q, const float* __restrict__ K,
    const float* __restrict__ V, float* __restrict__ O) {
    extern __shared__ float sm[];
    float* Qs = sm;                       // [64][64], [d][i]
    float* KP = sm + 4096;                // [64][68], K:[d][j] then P:[i][j]
    float* Vs = sm + 4096 + 64 * 68;      // [64][68], [j][d]

    const int tid = threadIdx.x;
    const int tx = tid & 15;   // j (S phase) / d (PV phase)
    const int ty = tid >> 4;   // i
    const int b = blockIdx.z;
    const int h = blockIdx.y;
    const int i0 = blockIdx.x * 64;
    const size_t base = ((size_t)b * NC + h * NDK) * NL;
    const float* Qb = Q + base;
    const float* Kb = K + base;
    const float* Vb = V + base;

    // Load Q tile (scaled by 1/sqrt(64))
#pragma unroll
    for (int r = 0; r < 4; r++) {
        const int t4 = tid * 4 + r * 1024;
        const int d = t4 >> 6, i = t4 & 63;
        float4 q4 = *(const float4*)&Qb[(size_t)d * NL + i0 + i];
        q4.x *= 0.125f; q4.y *= 0.125f; q4.z *= 0.125f; q4.w *= 0.125f;
        *(float4*)&Qs[d * 64 + i] = q4;
    }

    float m_run[4], l_run[4], acc[4][4];
#pragma unroll
    for (int ii = 0; ii < 4; ii++) {
        m_run[ii] = -1e30f; l_run[ii] = 0.f;
#pragma unroll
        for (int dd = 0; dd < 4; dd++) acc[ii][dd] = 0.f;
    }

    for (int jt = 0; jt < 8; jt++) {
        const int j0 = jt * 64;
        __syncthreads();  // prev PV done (and Q tile visible on first iter)
#pragma unroll
        for (int r = 0; r < 4; r++) {
            const int t4 = tid * 4 + r * 1024;
            const int d = t4 >> 6, j = t4 & 63;
            *(float4*)&KP[d * 68 + j] = *(const float4*)&Kb[(size_t)d * NL + j0 + j];
            float4 v4 = *(const float4*)&Vb[(size_t)d * NL + j0 + j];
            Vs[(j + 0) * 68 + d] = v4.x;
            Vs[(j + 1) * 68 + d] = v4.y;
            Vs[(j + 2) * 68 + d] = v4.z;
            Vs[(j + 3) * 68 + d] = v4.w;
        }
        __syncthreads();

        // S = Q^T K  (each thread: 4 i x 4 j)
        float s[4][4];
#pragma unroll
        for (int ii = 0; ii < 4; ii++)
#pragma unroll
            for (int jj = 0; jj < 4; jj++) s[ii][jj] = 0.f;
#pragma unroll 8
        for (int d = 0; d < 64; d++) {
            float4 qa = *(const float4*)&Qs[d * 64 + ty * 4];
            float4 kb = *(const float4*)&KP[d * 68 + tx * 4];
            float qi[4] = {qa.x, qa.y, qa.z, qa.w};
            float kj[4] = {kb.x, kb.y, kb.z, kb.w};
#pragma unroll
            for (int ii = 0; ii < 4; ii++)
#pragma unroll
                for (int jj = 0; jj < 4; jj++) s[ii][jj] += qi[ii] * kj[jj];
        }
        __syncthreads();  // everyone done reading K tile from KP

        // Online softmax; write P into KP
#pragma unroll
        for (int ii = 0; ii < 4; ii++) {
            float tmax = fmaxf(fmaxf(s[ii][0], s[ii][1]), fmaxf(s[ii][2], s[ii][3]));
#pragma unroll
            for (int off = 8; off > 0; off >>= 1)
                tmax = fmaxf(tmax, __shfl_xor_sync(0xffffffffu, tmax, off));
            const float mn = fmaxf(m_run[ii], tmax);
            const float corr = __expf(m_run[ii] - mn);
            m_run[ii] = mn;
            float rs = 0.f;
#pragma unroll
            for (int jj = 0; jj < 4; jj++) {
                const float p = __expf(s[ii][jj] - mn);
                s[ii][jj] = p; rs += p;
            }
#pragma unroll
            for (int off = 8; off > 0; off >>= 1)
                rs += __shfl_xor_sync(0xffffffffu, rs, off);
            l_run[ii] = l_run[ii] * corr + rs;
#pragma unroll
            for (int dd = 0; dd < 4; dd++) acc[ii][dd] *= corr;
#pragma unroll
            for (int jj = 0; jj < 4; jj++)
                KP[(ty * 4 + ii) * 68 + tx * 4 + jj] = s[ii][jj];
        }
        __syncthreads();

        // O += P @ V^T : acc[ii][dd] over (i = ty*4+ii, d = tx*4+dd)
#pragma unroll 8
        for (int j = 0; j < 64; j++) {
            float4 vv = *(const float4*)&Vs[j * 68 + tx * 4];
            const float p0 = KP[(ty * 4 + 0) * 68 + j];
            const float p1 = KP[(ty * 4 + 1) * 68 + j];
            const float p2 = KP[(ty * 4 + 2) * 68 + j];
            const float p3 = KP[(ty * 4 + 3) * 68 + j];
            acc[0][0] += p0 * vv.x; acc[0][1] += p0 * vv.y; acc[0][2] += p0 * vv.z; acc[0][3] += p0 * vv.w;
            acc[1][0] += p1 * vv.x; acc[1][1] += p1 * vv.y; acc[1][2] += p1 * vv.z; acc[1][3] += p1 * vv.w;
            acc[2][0] += p2 * vv.x; acc[2][1] += p2 * vv.y; acc[2][2] += p2 * vv.z; acc[2][3] += p2 * vv.w;
            acc[3][0] += p3 * vv.x; acc[3][1] += p3 * vv.y; acc[3][2] += p3 * vv.z; acc[3][3] += p3 * vv.w;
        }
    }
    __syncthreads();

    // Stage output in Qs as [d][i] for coalesced store
    float inv[4];
#pragma unroll
    for (int ii = 0; ii < 4; ii++) inv[ii] = 1.f / l_run[ii];
#pragma unroll
    for (int ii = 0; ii < 4; ii++)
#pragma unroll
        for (int dd = 0; dd < 4; dd++)
            Qs[(tx * 4 + dd) * 64 + ty * 4 + ii] = acc[ii][dd] * inv[ii];
    __syncthreads();

    float* Ob = O + base;
#pragma unroll
    for (int r = 0; r < 4; r++) {
        const int t4 = tid * 4 + r * 1024;
        const int d = t4 >> 6, i = t4 & 63;
        *(float4*)&Ob[(size_t)d * NL + i0 + i] = *(const float4*)&Qs[d * 64 + i];
    }
}

// ---------------------------------------------------------------------------
extern "C" void kernel_launch(void* const* d_in, const int* in_sizes, int n_in,
                              void* d_out, int out_size) {
    (void)in_sizes; (void)n_in; (void)out_size;
    const float* query  = (const float*)d_in[0];
    const float* key    = (const float*)d_in[1];
    const float* value  = (const float*)d_in[2];
    const float* pos    = (const float*)d_in[3];
    const float* proj_w = (const float*)d_in[4];
    const float* proj_b = (const float*)d_in[5];
    const float* q_dw_w = (const float*)d_in[6];
    const float* q_dw_b = (const float*)d_in[7];
    const float* q_pw_w = (const float*)d_in[8];
    const float* q_pw_b = (const float*)d_in[9];
    const float* k_dw_w = (const float*)d_in[10];
    const float* k_dw_b = (const float*)d_in[11];
    const float* k_pw_w = (const float*)d_in[12];
    const float* k_pw_b = (const float*)d_in[13];
    const float* v_dw_w = (const float*)d_in[14];
    const float* v_dw_b = (const float*)d_in[15];
    const float* v_pw_w = (const float*)d_in[16];
    const float* v_pw_b = (const float*)d_in[17];

    float *t, *q, *k, *v, *o, *posT;
    cudaGetSymbolAddress((void**)&t, g_t);
    cudaGetSymbolAddress((void**)&q, g_q);
    cudaGetSymbolAddress((void**)&k, g_k);
    cudaGetSymbolAddress((void**)&v, g_v);
    cudaGetSymbolAddress((void**)&o, g_o);
    cudaGetSymbolAddress((void**)&posT, g_post);

    cudaFuncSetAttribute(attn_kernel,
                         cudaFuncAttributeMaxDynamicSharedMemorySize, 51200);

    transpose_pos_kernel<<<dim3(16, 16), dim3(32, 8)>>>(pos, posT);

    dwconv_kernel<<<dim3(NC, NB), 512>>>(query, posT, q_dw_w, q_dw_b, t, 1);
    gemm_nn_kernel<<<dim3(8, 4, NB), 256>>>(q_pw_w, t, q_pw_b, q);

    dwconv_kernel<<<dim3(NC, NB), 512>>>(key, posT, k_dw_w, k_dw_b, t, 1);
    gemm_nn_kernel<<<dim3(8, 4, NB), 256>>>(k_pw_w, t, k_pw_b, k);

    dwconv_kernel<<<dim3(NC, NB), 512>>>(value, posT, v_dw_w, v_dw_b, t, 0);
    gemm_nn_kernel<<<dim3(8, 4, NB), 256>>>(v_pw_w, t, v_pw_b, v);

    attn_kernel<<<dim3(NL / 64, NH, NB), 256, 51200>>>(q, k, v, o);

    gemm_nt_kernel<<<dim3(8, 4, NB), 256>>>(o, proj_w, proj_b, (float*)d_out);
}

// round 3
// speedup vs baseline: 1.9440x; 1.9440x over previous
#include <cuda_runtime.h>
#include <cstdint>

#define NB 32
#define NC 512
#define NL 512
#define NH 8
#define NDK 64
#define LC (512 * 512)

// Scratch (device globals: no allocations allowed)
__device__ float g_t[NB * NC * NL];      // dwconv output, TRANSPOSED: (b, l, c)
__device__ float g_q[NB * NC * NL];      // (b, o, l)
__device__ float g_k[NB * NC * NL];
__device__ float g_v[NB * NC * NL];
__device__ float g_o[NB * NC * NL];      // attention output (b, c, i)
__device__ float g_post[NC * NL];        // pos_bias transposed to (C, L)

__device__ __forceinline__ float to_tf32(float x) {
    uint32_t u;
    asm("cvt.rna.tf32.f32 %0, %1;" : "=r"(u) : "f"(x));
    return __uint_as_float(u);
}

// mma.sync m16n8k8 tf32 (legacy tensor path — valid on plain sm_103 target)
__device__ __forceinline__ void mma_tf32(float* d, const uint32_t* a, const uint32_t* b) {
    asm volatile(
        "mma.sync.aligned.m16n8k8.row.col.f32.tf32.tf32.f32 "
        "{%0,%1,%2,%3}, {%4,%5,%6,%7}, {%8,%9}, {%0,%1,%2,%3};"
        : "+f"(d[0]), "+f"(d[1]), "+f"(d[2]), "+f"(d[3])
        : "r"(a[0]), "r"(a[1]), "r"(a[2]), "r"(a[3]), "r"(b[0]), "r"(b[1]));
}

// ===========================================================================
// pos_bias (L, C) -> posT (C, L)
// ===========================================================================
__global__ void transpose_pos_kernel(const float* __restrict__ pos,
                                     float* __restrict__ posT) {
    __shared__ float tile[32][33];
    const int c0 = blockIdx.x * 32;
    const int l0 = blockIdx.y * 32;
    const int tx = threadIdx.x;
    const int ty = threadIdx.y;
#pragma unroll
    for (int r = 0; r < 4; r++)
        tile[ty + r * 8][tx] = pos[(size_t)(l0 + ty + r * 8) * NC + c0 + tx];
    __syncthreads();
#pragma unroll
    for (int r = 0; r < 4; r++)
        posT[(size_t)(c0 + ty + r * 8) * NL + l0 + tx] = tile[tx][ty + r * 8];
}

// ===========================================================================
// depthwise conv1d (K=7, pad=3) + optional pos-bias add, TRANSPOSED output.
// Block: (c-tile of 32, batch). Output y[b, l, c] (c contiguous).
// ===========================================================================
#define XST 521
__global__ __launch_bounds__(256) void dwconv_t_kernel(
    const float* __restrict__ x, const float* __restrict__ posT,
    const float* __restrict__ w, const float* __restrict__ bias,
    float* __restrict__ y, int add_pos) {
    extern __shared__ float xs[];  // [32][XST]; data at xs[cc*XST + 4 + l]
    const int tid = threadIdx.x;
    const int c0 = blockIdx.x * 32;
    const int b = blockIdx.y;

    const int cc = tid & 31;
    const int ly = tid >> 5;
    float wt[7];
#pragma unroll
    for (int t = 0; t < 7; t++) wt[t] = w[(c0 + cc) * 7 + t];
    const float bs = bias[c0 + cc];

    {
        const int lr = tid >> 3;
        const int seg = tid & 7;
        const float* xrow = x + ((size_t)b * NC + c0 + lr) * NL + seg * 64;
        const float* prow = posT + (size_t)(c0 + lr) * NL + seg * 64;
        float* xd = xs + lr * XST + 4 + seg * 64;
#pragma unroll
        for (int i = 0; i < 16; i++) {
            float4 v = *(const float4*)&xrow[i * 4];
            if (add_pos) {
                float4 p = *(const float4*)&prow[i * 4];
                v.x += p.x; v.y += p.y; v.z += p.z; v.w += p.w;
            }
            xd[i * 4 + 0] = v.x; xd[i * 4 + 1] = v.y;
            xd[i * 4 + 2] = v.z; xd[i * 4 + 3] = v.w;
        }
        if (seg == 0) {
            xs[lr * XST + 1] = 0.f; xs[lr * XST + 2] = 0.f; xs[lr * XST + 3] = 0.f;
            xs[lr * XST + 516] = 0.f; xs[lr * XST + 517] = 0.f; xs[lr * XST + 518] = 0.f;
        }
    }
    __syncthreads();

    const float* xr = xs + cc * XST;
    const int base = ly * 64;
    float win[7];
#pragma unroll
    for (int t = 0; t < 6; t++) win[t] = xr[base + 1 + t];
    float* yb = y + (size_t)b * LC + c0 + cc;
#pragma unroll
    for (int r = 0; r < 64; r++) {
        const int l = base + r;
        win[6] = xr[l + 7];
        float acc = bs;
#pragma unroll
        for (int t = 0; t < 7; t++) acc += win[t] * wt[t];
        yb[(size_t)l * NC] = acc;
#pragma unroll
        for (int t = 0; t < 6; t++) win[t] = win[t + 1];
    }
}

// ===========================================================================
// Batched GEMM via mma.sync tf32: Y[z][m][n] = sum_k A[z][m][k] * B[z][n][k]
// M=N=K=512. CTA tile 128x128, BK=16, 256 threads (8 warps, 2m x 4n),
// warp tile 64x32 = 16 m16n8k8 atoms. Smem k-permuted so each fragment
// (k, k+4) pair is one float2 LDS.
// ===========================================================================
#define PK 20  // padded row stride (floats) for BK=16
__global__ __launch_bounds__(256) void gemm_mma_kernel(
    const float* __restrict__ A, long aStride,
    const float* __restrict__ B, long bStride,
    const float* __restrict__ bias, int biasPerM,
    float* __restrict__ Y) {
    __shared__ float As[128 * PK];
    __shared__ float Bs[128 * PK];

    const int tid = threadIdx.x;
    const int lane = tid & 31;
    const int g = lane >> 2;      // 0..7
    const int tg = lane & 3;      // 0..3
    const int wm = (tid >> 5) >> 2;  // 0..1
    const int wn = (tid >> 5) & 3;   // 0..3
    const int n0 = blockIdx.x * 128;
    const int m0 = blockIdx.y * 128;
    const int z = blockIdx.z;
    const float* Ab = A + (size_t)z * aStride;
    const float* Bb = B + (size_t)z * bStride;

    // global stage identity: row = tid>>1 (0..127), half = tid&1 (k-offset 8*half)
    const int lrow = tid >> 1;
    const int lhalf = tid & 1;
    const float* Arow = Ab + (size_t)(m0 + lrow) * 512 + lhalf * 8;
    const float* Brow = Bb + (size_t)(n0 + lrow) * 512 + lhalf * 8;
    float* ad = &As[lrow * PK + lhalf * 8];
    float* bd = &Bs[lrow * PK + lhalf * 8];

    float acc[4][4][4];
#pragma unroll
    for (int mi = 0; mi < 4; mi++)
#pragma unroll
        for (int ni = 0; ni < 4; ni++)
#pragma unroll
            for (int r = 0; r < 4; r++) acc[mi][ni][r] = 0.f;

    // prologue: stage chunk 0
    float4 a0r = *(const float4*)&Arow[0];
    float4 a1r = *(const float4*)&Arow[4];
    float4 b0r = *(const float4*)&Brow[0];
    float4 b1r = *(const float4*)&Brow[4];

    for (int kc = 0; kc < 32; kc++) {
        __syncthreads();  // previous compute done reading smem
        // k-permuted store: pos = (j&3)*2 + (j>>2)
        ad[0] = to_tf32(a0r.x); ad[2] = to_tf32(a0r.y);
        ad[4] = to_tf32(a0r.z); ad[6] = to_tf32(a0r.w);
        ad[1] = to_tf32(a1r.x); ad[3] = to_tf32(a1r.y);
        ad[5] = to_tf32(a1r.z); ad[7] = to_tf32(a1r.w);
        bd[0] = to_tf32(b0r.x); bd[2] = to_tf32(b0r.y);
        bd[4] = to_tf32(b0r.z); bd[6] = to_tf32(b0r.w);
        bd[1] = to_tf32(b1r.x); bd[3] = to_tf32(b1r.y);
        bd[5] = to_tf32(b1r.z); bd[7] = to_tf32(b1r.w);
        __syncthreads();
        if (kc < 31) {
            const int k0n = (kc + 1) * 16;
            a0r = *(const float4*)&Arow[k0n];
            a1r = *(const float4*)&Arow[k0n + 4];
            b0r = *(const float4*)&Brow[k0n];
            b1r = *(const float4*)&Brow[k0n + 4];
        }
#pragma unroll
        for (int s = 0; s < 2; s++) {
            uint32_t af[4][4];
#pragma unroll
            for (int mi = 0; mi < 4; mi++) {
                const float* p = &As[(wm * 64 + mi * 16 + g) * PK + s * 8 + 2 * tg];
                float2 p0 = *(const float2*)p;
                float2 p1 = *(const float2*)(p + 8 * PK);
                af[mi][0] = __float_as_uint(p0.x);
                af[mi][1] = __float_as_uint(p1.x);
                af[mi][2] = __float_as_uint(p0.y);
                af[mi][3] = __float_as_uint(p1.y);
            }
            uint32_t bf[4][2];
#pragma unroll
            for (int ni = 0; ni < 4; ni++) {
                float2 q = *(const float2*)&Bs[(wn * 32 + ni * 8 + g) * PK + s * 8 + 2 * tg];
                bf[ni][0] = __float_as_uint(q.x);
                bf[ni][1] = __float_as_uint(q.y);
            }
#pragma unroll
            for (int mi = 0; mi < 4; mi++)
#pragma unroll
                for (int ni = 0; ni < 4; ni++)
                    mma_tf32(acc[mi][ni], af[mi], bf[ni]);
        }
    }

    // epilogue
    float* Yb = Y + (size_t)z * LC;
#pragma unroll
    for (int mi = 0; mi < 4; mi++) {
        const int m = m0 + wm * 64 + mi * 16 + g;
#pragma unroll
        for (int ni = 0; ni < 4; ni++) {
            const int n = n0 + wn * 32 + ni * 8 + 2 * tg;
            float c0 = acc[mi][ni][0], c1 = acc[mi][ni][1];
            float c2 = acc[mi][ni][2], c3 = acc[mi][ni][3];
            if (biasPerM) {
                const float bm0 = bias[m], bm1 = bias[m + 8];
                c0 += bm0; c1 += bm0; c2 += bm1; c3 += bm1;
            } else {
                const float bn0 = bias[n], bn1 = bias[n + 1];
                c0 += bn0; c1 += bn1; c2 += bn0; c3 += bn1;
            }
            float2 o0 = {c0, c1}, o1 = {c2, c3};
            *(float2*)&Yb[(size_t)m * 512 + n] = o0;
            *(float2*)&Yb[(size_t)(m + 8) * 512 + n] = o1;
        }
    }
}

// ===========================================================================
// Flash-style SIMT attention (proven correct in R1)
// ===========================================================================
__global__ __launch_bounds__(256) void attn_kernel(
    const float* __restrict__ Q, const float* __restrict__ K,
    const float* __restrict__ V, float* __restrict__ O) {
    extern __shared__ float sm[];
    float* Qs = sm;
    float* KP = sm + 4096;
    float* Vs = sm + 4096 + 64 * 68;

    const int tid = threadIdx.x;
    const int tx = tid & 15;
    const int ty = tid >> 4;
    const int b = blockIdx.z;
    const int h = blockIdx.y;
    const int i0 = blockIdx.x * 64;
    const size_t base = ((size_t)b * NC + h * NDK) * NL;
    const float* Qb = Q + base;
    const float* Kb = K + base;
    const float* Vb = V + base;

#pragma unroll
    for (int r = 0; r < 4; r++) {
        const int t4 = tid * 4 + r * 1024;
        const int d = t4 >> 6, i = t4 & 63;
        float4 q4 = *(const float4*)&Qb[(size_t)d * NL + i0 + i];
        q4.x *= 0.125f; q4.y *= 0.125f; q4.z *= 0.125f; q4.w *= 0.125f;
        *(float4*)&Qs[d * 64 + i] = q4;
    }

    float m_run[4], l_run[4], acc[4][4];
#pragma unroll
    for (int ii = 0; ii < 4; ii++) {
        m_run[ii] = -1e30f; l_run[ii] = 0.f;
#pragma unroll
        for (int dd = 0; dd < 4; dd++) acc[ii][dd] = 0.f;
    }

    for (int jt = 0; jt < 8; jt++) {
        const int j0 = jt * 64;
        __syncthreads();
#pragma unroll
        for (int r = 0; r < 4; r++) {
            const int t4 = tid * 4 + r * 1024;
            const int d = t4 >> 6, j = t4 & 63;
            *(float4*)&KP[d * 68 + j] = *(const float4*)&Kb[(size_t)d * NL + j0 + j];
            float4 v4 = *(const float4*)&Vb[(size_t)d * NL + j0 + j];
            Vs[(j + 0) * 68 + d] = v4.x;
            Vs[(j + 1) * 68 + d] = v4.y;
            Vs[(j + 2) * 68 + d] = v4.z;
            Vs[(j + 3) * 68 + d] = v4.w;
        }
        __syncthreads();

        float s[4][4];
#pragma unroll
        for (int ii = 0; ii < 4; ii++)
#pragma unroll
            for (int jj = 0; jj < 4; jj++) s[ii][jj] = 0.f;
#pragma unroll 8
        for (int d = 0; d < 64; d++) {
            float4 qa = *(const float4*)&Qs[d * 64 + ty * 4];
            float4 kb = *(const float4*)&KP[d * 68 + tx * 4];
            float qi[4] = {qa.x, qa.y, qa.z, qa.w};
            float kj[4] = {kb.x, kb.y, kb.z, kb.w};
#pragma unroll
            for (int ii = 0; ii < 4; ii++)
#pragma unroll
                for (int jj = 0; jj < 4; jj++) s[ii][jj] += qi[ii] * kj[jj];
        }
        __syncthreads();

#pragma unroll
        for (int ii = 0; ii < 4; ii++) {
            float tmax = fmaxf(fmaxf(s[ii][0], s[ii][1]), fmaxf(s[ii][2], s[ii][3]));
#pragma unroll
            for (int off = 8; off > 0; off >>= 1)
                tmax = fmaxf(tmax, __shfl_xor_sync(0xffffffffu, tmax, off));
            const float mn = fmaxf(m_run[ii], tmax);
            const float corr = __expf(m_run[ii] - mn);
            m_run[ii] = mn;
            float rs = 0.f;
#pragma unroll
            for (int jj = 0; jj < 4; jj++) {
                const float p = __expf(s[ii][jj] - mn);
                s[ii][jj] = p; rs += p;
            }
#pragma unroll
            for (int off = 8; off > 0; off >>= 1)
                rs += __shfl_xor_sync(0xffffffffu, rs, off);
            l_run[ii] = l_run[ii] * corr + rs;
#pragma unroll
            for (int dd = 0; dd < 4; dd++) acc[ii][dd] *= corr;
#pragma unroll
            for (int jj = 0; jj < 4; jj++)
                KP[(ty * 4 + ii) * 68 + tx * 4 + jj] = s[ii][jj];
        }
        __syncthreads();

#pragma unroll 8
        for (int j = 0; j < 64; j++) {
            float4 vv = *(const float4*)&Vs[j * 68 + tx * 4];
            const float p0 = KP[(ty * 4 + 0) * 68 + j];
            const float p1 = KP[(ty * 4 + 1) * 68 + j];
            const float p2 = KP[(ty * 4 + 2) * 68 + j];
            const float p3 = KP[(ty * 4 + 3) * 68 + j];
            acc[0][0] += p0 * vv.x; acc[0][1] += p0 * vv.y; acc[0][2] += p0 * vv.z; acc[0][3] += p0 * vv.w;
            acc[1][0] += p1 * vv.x; acc[1][1] += p1 * vv.y; acc[1][2] += p1 * vv.z; acc[1][3] += p1 * vv.w;
            acc[2][0] += p2 * vv.x; acc[2][1] += p2 * vv.y; acc[2][2] += p2 * vv.z; acc[2][3] += p2 * vv.w;
            acc[3][0] += p3 * vv.x; acc[3][1] += p3 * vv.y; acc[3][2] += p3 * vv.z; acc[3][3] += p3 * vv.w;
        }
    }
    __syncthreads();

    float inv[4];
#pragma unroll
    for (int ii = 0; ii < 4; ii++) inv[ii] = 1.f / l_run[ii];
#pragma unroll
    for (int ii = 0; ii < 4; ii++)
#pragma unroll
        for (int dd = 0; dd < 4; dd++)
            Qs[(tx * 4 + dd) * 64 + ty * 4 + ii] = acc[ii][dd] * inv[ii];
    __syncthreads();

    float* Ob = O + base;
#pragma unroll
    for (int r = 0; r < 4; r++) {
        const int t4 = tid * 4 + r * 1024;
        const int d = t4 >> 6, i = t4 & 63;
        *(float4*)&Ob[(size_t)d * NL + i0 + i] = *(const float4*)&Qs[d * 64 + i];
    }
}

// ===========================================================================
extern "C" void kernel_launch(void* const* d_in, const int* in_sizes, int n_in,
                              void* d_out, int out_size) {
    (void)in_sizes; (void)n_in; (void)out_size;
    const float* query  = (const float*)d_in[0];
    const float* key    = (const float*)d_in[1];
    const float* value  = (const float*)d_in[2];
    const float* pos    = (const float*)d_in[3];
    const float* proj_w = (const float*)d_in[4];
    const float* proj_b = (const float*)d_in[5];
    const float* q_dw_w = (const float*)d_in[6];
    const float* q_dw_b = (const float*)d_in[7];
    const float* q_pw_w = (const float*)d_in[8];
    const float* q_pw_b = (const float*)d_in[9];
    const float* k_dw_w = (const float*)d_in[10];
    const float* k_dw_b = (const float*)d_in[11];
    const float* k_pw_w = (const float*)d_in[12];
    const float* k_pw_b = (const float*)d_in[13];
    const float* v_dw_w = (const float*)d_in[14];
    const float* v_dw_b = (const float*)d_in[15];
    const float* v_pw_w = (const float*)d_in[16];
    const float* v_pw_b = (const float*)d_in[17];

    float *t, *q, *k, *v, *o, *posT;
    cudaGetSymbolAddress((void**)&t, g_t);
    cudaGetSymbolAddress((void**)&q, g_q);
    cudaGetSymbolAddress((void**)&k, g_k);
    cudaGetSymbolAddress((void**)&v, g_v);
    cudaGetSymbolAddress((void**)&o, g_o);
    cudaGetSymbolAddress((void**)&posT, g_post);

    const int dsm = 32 * XST * 4;
    cudaFuncSetAttribute(dwconv_t_kernel,
                         cudaFuncAttributeMaxDynamicSharedMemorySize, dsm);
    cudaFuncSetAttribute(attn_kernel,
                         cudaFuncAttributeMaxDynamicSharedMemorySize, 51200);

    transpose_pos_kernel<<<dim3(16, 16), dim3(32, 8)>>>(pos, posT);

    // q path
    dwconv_t_kernel<<<dim3(16, NB), 256, dsm>>>(query, posT, q_dw_w, q_dw_b, t, 1);
    gemm_mma_kernel<<<dim3(4, 4, NB), 256>>>(q_pw_w, 0L, t, (long)LC, q_pw_b, 1, q);
    // k path
    dwconv_t_kernel<<<dim3(16, NB), 256, dsm>>>(key, posT, k_dw_w, k_dw_b, t, 1);
    gemm_mma_kernel<<<dim3(4, 4, NB), 256>>>(k_pw_w, 0L, t, (long)LC, k_pw_b, 1, k);
    // v path
    dwconv_t_kernel<<<dim3(16, NB), 256, dsm>>>(value, posT, v_dw_w, v_dw_b, t, 0);
    gemm_mma_kernel<<<dim3(4, 4, NB), 256>>>(v_pw_w, 0L, t, (long)LC, v_pw_b, 1, v);
    // attention (SIMT fp32)
    attn_kernel<<<dim3(NL / 64, NH, NB), 256, 51200>>>(q, k, v, o);
    // final projection
    gemm_mma_kernel<<<dim3(4, 4, NB), 256>>>(o, (long)LC, proj_w, 0L, proj_b, 0, (float*)d_out);
}

// round 4
// speedup vs baseline: 2.5113x; 1.2918x over previous
#include <cuda_runtime.h>
#include <cstdint>

#define NB 32
#define NC 512
#define NL 512
#define NH 8
#define NDK 64
#define LC (512 * 512)

// Scratch (device globals: no allocations allowed)
__device__ float g_t[NB * NC * NL];      // dwconv output, (b, l, c)
__device__ float g_q[NB * NC * NL];      // (b, l, c)
__device__ float g_k[NB * NC * NL];
__device__ float g_v[NB * NC * NL];
__device__ float g_o[NB * NC * NL];      // attention output (b, c, i)
__device__ float g_post[NC * NL];        // pos_bias transposed to (C, L)

__device__ __forceinline__ float to_tf32(float x) {
    uint32_t u;
    asm("cvt.rna.tf32.f32 %0, %1;" : "=r"(u) : "f"(x));
    return __uint_as_float(u);
}

__device__ __forceinline__ void mma_tf32(float* d, const uint32_t* a, const uint32_t* b) {
    asm volatile(
        "mma.sync.aligned.m16n8k8.row.col.f32.tf32.tf32.f32 "
        "{%0,%1,%2,%3}, {%4,%5,%6,%7}, {%8,%9}, {%0,%1,%2,%3};"
        : "+f"(d[0]), "+f"(d[1]), "+f"(d[2]), "+f"(d[3])
        : "r"(a[0]), "r"(a[1]), "r"(a[2]), "r"(a[3]), "r"(b[0]), "r"(b[1]));
}

// ===========================================================================
// pos_bias (L, C) -> posT (C, L)
// ===========================================================================
__global__ void transpose_pos_kernel(const float* __restrict__ pos,
                                     float* __restrict__ posT) {
    __shared__ float tile[32][33];
    const int c0 = blockIdx.x * 32;
    const int l0 = blockIdx.y * 32;
    const int tx = threadIdx.x;
    const int ty = threadIdx.y;
#pragma unroll
    for (int r = 0; r < 4; r++)
        tile[ty + r * 8][tx] = pos[(size_t)(l0 + ty + r * 8) * NC + c0 + tx];
    __syncthreads();
#pragma unroll
    for (int r = 0; r < 4; r++)
        posT[(size_t)(c0 + ty + r * 8) * NL + l0 + tx] = tile[tx][ty + r * 8];
}

// ===========================================================================
// depthwise conv1d (K=7, pad=3) + optional pos-bias add, TRANSPOSED output.
// Output y[b, l, c].
// ===========================================================================
#define XST 521
__global__ __launch_bounds__(256) void dwconv_t_kernel(
    const float* __restrict__ x, const float* __restrict__ posT,
    const float* __restrict__ w, const float* __restrict__ bias,
    float* __restrict__ y, int add_pos) {
    extern __shared__ float xs[];
    const int tid = threadIdx.x;
    const int c0 = blockIdx.x * 32;
    const int b = blockIdx.y;

    const int cc = tid & 31;
    const int ly = tid >> 5;
    float wt[7];
#pragma unroll
    for (int t = 0; t < 7; t++) wt[t] = w[(c0 + cc) * 7 + t];
    const float bs = bias[c0 + cc];

    {
        const int lr = tid >> 3;
        const int seg = tid & 7;
        const float* xrow = x + ((size_t)b * NC + c0 + lr) * NL + seg * 64;
        const float* prow = posT + (size_t)(c0 + lr) * NL + seg * 64;
        float* xd = xs + lr * XST + 4 + seg * 64;
#pragma unroll
        for (int i = 0; i < 16; i++) {
            float4 v = *(const float4*)&xrow[i * 4];
            if (add_pos) {
                float4 p = *(const float4*)&prow[i * 4];
                v.x += p.x; v.y += p.y; v.z += p.z; v.w += p.w;
            }
            xd[i * 4 + 0] = v.x; xd[i * 4 + 1] = v.y;
            xd[i * 4 + 2] = v.z; xd[i * 4 + 3] = v.w;
        }
        if (seg == 0) {
            xs[lr * XST + 1] = 0.f; xs[lr * XST + 2] = 0.f; xs[lr * XST + 3] = 0.f;
            xs[lr * XST + 516] = 0.f; xs[lr * XST + 517] = 0.f; xs[lr * XST + 518] = 0.f;
        }
    }
    __syncthreads();

    const float* xr = xs + cc * XST;
    const int base = ly * 64;
    float win[7];
#pragma unroll
    for (int t = 0; t < 6; t++) win[t] = xr[base + 1 + t];
    float* yb = y + (size_t)b * LC + c0 + cc;
#pragma unroll
    for (int r = 0; r < 64; r++) {
        const int l = base + r;
        win[6] = xr[l + 7];
        float acc = bs;
#pragma unroll
        for (int t = 0; t < 7; t++) acc += win[t] * wt[t];
        yb[(size_t)l * NC] = acc;
#pragma unroll
        for (int t = 0; t < 6; t++) win[t] = win[t + 1];
    }
}

// ===========================================================================
// Batched GEMM (tf32 mma): Y[z][m][n] = sum_k A[z][m][k] * W[n][k] + bias[n]
// A batched row-major (stride aStride), W shared row-major (n,k).
// CTA 128x128, BK=16, double-buffered smem, 256 thr (8 warps 2m x 4n),
// unpermuted smem (float4 STS, conflict-free scalar LDS fragments).
// ===========================================================================
#define PK 20
__global__ __launch_bounds__(256) void gemm_mma_kernel(
    const float* __restrict__ A, long aStride,
    const float* __restrict__ W,
    const float* __restrict__ bias,
    float* __restrict__ Y) {
    __shared__ float As[2][128 * PK];
    __shared__ float Bs[2][128 * PK];

    const int tid = threadIdx.x;
    const int lane = tid & 31;
    const int g = lane >> 2;
    const int tg = lane & 3;
    const int wm = (tid >> 5) >> 2;
    const int wn = (tid >> 5) & 3;
    const int n0 = blockIdx.x * 128;
    const int m0 = blockIdx.y * 128;
    const int z = blockIdx.z;
    const float* Ab = A + (size_t)z * aStride;

    const int lrow = tid >> 1;
    const int lhalf = tid & 1;
    const float* Arow = Ab + (size_t)(m0 + lrow) * 512 + lhalf * 8;
    const float* Brow = W + (size_t)(n0 + lrow) * 512 + lhalf * 8;
    const int soff = lrow * PK + lhalf * 8;

    float acc[4][4][4];
#pragma unroll
    for (int mi = 0; mi < 4; mi++)
#pragma unroll
        for (int ni = 0; ni < 4; ni++)
#pragma unroll
            for (int r = 0; r < 4; r++) acc[mi][ni][r] = 0.f;

    float4 a0r = *(const float4*)&Arow[0];
    float4 a1r = *(const float4*)&Arow[4];
    float4 b0r = *(const float4*)&Brow[0];
    float4 b1r = *(const float4*)&Brow[4];
    {
        float4 t0 = {to_tf32(a0r.x), to_tf32(a0r.y), to_tf32(a0r.z), to_tf32(a0r.w)};
        float4 t1 = {to_tf32(a1r.x), to_tf32(a1r.y), to_tf32(a1r.z), to_tf32(a1r.w)};
        float4 t2 = {to_tf32(b0r.x), to_tf32(b0r.y), to_tf32(b0r.z), to_tf32(b0r.w)};
        float4 t3 = {to_tf32(b1r.x), to_tf32(b1r.y), to_tf32(b1r.z), to_tf32(b1r.w)};
        *(float4*)&As[0][soff] = t0; *(float4*)&As[0][soff + 4] = t1;
        *(float4*)&Bs[0][soff] = t2; *(float4*)&Bs[0][soff + 4] = t3;
    }
    __syncthreads();

    for (int kc = 0; kc < 32; kc++) {
        const int cur = kc & 1;
        if (kc < 31) {
            const int k0n = (kc + 1) * 16;
            a0r = *(const float4*)&Arow[k0n];
            a1r = *(const float4*)&Arow[k0n + 4];
            b0r = *(const float4*)&Brow[k0n];
            b1r = *(const float4*)&Brow[k0n + 4];
        }
#pragma unroll
        for (int s = 0; s < 2; s++) {
            uint32_t af[4][4];
#pragma unroll
            for (int mi = 0; mi < 4; mi++) {
                const float* p = &As[cur][(wm * 64 + mi * 16 + g) * PK + s * 8 + tg];
                af[mi][0] = __float_as_uint(p[0]);
                af[mi][1] = __float_as_uint(p[8 * PK]);
                af[mi][2] = __float_as_uint(p[4]);
                af[mi][3] = __float_as_uint(p[8 * PK + 4]);
            }
            uint32_t bf[4][2];
#pragma unroll
            for (int ni = 0; ni < 4; ni++) {
                const float* q = &Bs[cur][(wn * 32 + ni * 8 + g) * PK + s * 8 + tg];
                bf[ni][0] = __float_as_uint(q[0]);
                bf[ni][1] = __float_as_uint(q[4]);
            }
#pragma unroll
            for (int mi = 0; mi < 4; mi++)
#pragma unroll
                for (int ni = 0; ni < 4; ni++)
                    mma_tf32(acc[mi][ni], af[mi], bf[ni]);
        }
        if (kc < 31) {
            const int nxt = cur ^ 1;
            float4 t0 = {to_tf32(a0r.x), to_tf32(a0r.y), to_tf32(a0r.z), to_tf32(a0r.w)};
            float4 t1 = {to_tf32(a1r.x), to_tf32(a1r.y), to_tf32(a1r.z), to_tf32(a1r.w)};
            float4 t2 = {to_tf32(b0r.x), to_tf32(b0r.y), to_tf32(b0r.z), to_tf32(b0r.w)};
            float4 t3 = {to_tf32(b1r.x), to_tf32(b1r.y), to_tf32(b1r.z), to_tf32(b1r.w)};
            *(float4*)&As[nxt][soff] = t0; *(float4*)&As[nxt][soff + 4] = t1;
            *(float4*)&Bs[nxt][soff] = t2; *(float4*)&Bs[nxt][soff + 4] = t3;
        }
        __syncthreads();
    }

    float* Yb = Y + (size_t)z * LC;
#pragma unroll
    for (int mi = 0; mi < 4; mi++) {
        const int m = m0 + wm * 64 + mi * 16 + g;
#pragma unroll
        for (int ni = 0; ni < 4; ni++) {
            const int n = n0 + wn * 32 + ni * 8 + 2 * tg;
            const float bn0 = bias[n], bn1 = bias[n + 1];
            float2 o0 = {acc[mi][ni][0] + bn0, acc[mi][ni][1] + bn1};
            float2 o1 = {acc[mi][ni][2] + bn0, acc[mi][ni][3] + bn1};
            *(float2*)&Yb[(size_t)m * 512 + n] = o0;
            *(float2*)&Yb[(size_t)(m + 8) * 512 + n] = o1;
        }
    }
}

// ===========================================================================
// Flash attention on tensor cores (tf32 mma). Inputs Q,K,V in (b, l, c).
// CTA = (i-tile of 64, h, b), 128 threads (4 warps, 16 i-rows each).
// Output O in (b, c, i).
// smem: Qs[64][AS2] (d-permuted, scaled), KP[64][AS2] (K d-permuted, then
// P j-permuted), Vs[64][AS2] (plain [j][d]).
// ===========================================================================
#define AS2 68
__global__ __launch_bounds__(128) void attn_mma_kernel(
    const float* __restrict__ Q, const float* __restrict__ K,
    const float* __restrict__ V, float* __restrict__ O) {
    extern __shared__ float sm[];
    float* Qs = sm;
    float* KP = sm + 64 * AS2;
    float* Vs = sm + 2 * 64 * AS2;

    const int tid = threadIdx.x;
    const int w = tid >> 5;
    const int lane = tid & 31;
    const int g = lane >> 2;
    const int tg = lane & 3;
    const int b = blockIdx.z;
    const int h = blockIdx.y;
    const int i0 = blockIdx.x * 64;

    const float* Qb = Q + (size_t)b * LC + h * 64;
    const float* Kb = K + (size_t)b * LC + h * 64;
    const float* Vb = V + (size_t)b * LC + h * 64;

    const int row = tid >> 1;
    const int half = tid & 1;

    // Load Q tile: perm-d layout, scaled by 1/8, tf32
    {
        const float* src = Qb + (size_t)(i0 + row) * 512 + half * 32;
        float* dst = Qs + row * AS2 + half * 32;
#pragma unroll
        for (int u = 0; u < 8; u++) {
            float4 x = *(const float4*)&src[u * 4];
            float* d8 = dst + (u >> 1) * 8 + (u & 1);
            d8[0] = to_tf32(x.x * 0.125f);
            d8[2] = to_tf32(x.y * 0.125f);
            d8[4] = to_tf32(x.z * 0.125f);
            d8[6] = to_tf32(x.w * 0.125f);
        }
    }

    float m_run0 = -1e30f, m_run1 = -1e30f, l_run0 = 0.f, l_run1 = 0.f;
    float oacc[8][4];
#pragma unroll
    for (int nt = 0; nt < 8; nt++)
#pragma unroll
        for (int r = 0; r < 4; r++) oacc[nt][r] = 0.f;

    const int pr0 = (w * 16 + g) * AS2;
    const int pr1 = pr0 + 8 * AS2;
    const int pos0 = ((2 * tg) & 3) * 2 + ((2 * tg) >> 2);

    for (int jt = 0; jt < 8; jt++) {
        const int j0 = jt * 64;
        __syncthreads();  // prev iter PV done (+ Q load on first iter)
        {
            const float* ks = Kb + (size_t)(j0 + row) * 512 + half * 32;
            float* kd = KP + row * AS2 + half * 32;
            const float* vsrc = Vb + (size_t)(j0 + row) * 512 + half * 32;
            float* vd = Vs + row * AS2 + half * 32;
#pragma unroll
            for (int u = 0; u < 8; u++) {
                float4 x = *(const float4*)&ks[u * 4];
                float* d8 = kd + (u >> 1) * 8 + (u & 1);
                d8[0] = to_tf32(x.x); d8[2] = to_tf32(x.y);
                d8[4] = to_tf32(x.z); d8[6] = to_tf32(x.w);
                float4 y = *(const float4*)&vsrc[u * 4];
                float4 t = {to_tf32(y.x), to_tf32(y.y), to_tf32(y.z), to_tf32(y.w)};
                *(float4*)&vd[u * 4] = t;
            }
        }
        __syncthreads();

        // S = Q K^T (scaled)
        float sacc[8][4];
#pragma unroll
        for (int nt = 0; nt < 8; nt++)
#pragma unroll
            for (int r = 0; r < 4; r++) sacc[nt][r] = 0.f;
#pragma unroll
        for (int k0 = 0; k0 < 8; k0++) {
            float2 aA = *(const float2*)&Qs[pr0 + k0 * 8 + 2 * tg];
            float2 aB = *(const float2*)&Qs[pr1 + k0 * 8 + 2 * tg];
            uint32_t af[4] = {__float_as_uint(aA.x), __float_as_uint(aB.x),
                              __float_as_uint(aA.y), __float_as_uint(aB.y)};
#pragma unroll
            for (int nt = 0; nt < 8; nt++) {
                float2 bb = *(const float2*)&KP[(nt * 8 + g) * AS2 + k0 * 8 + 2 * tg];
                uint32_t bf[2] = {__float_as_uint(bb.x), __float_as_uint(bb.y)};
                mma_tf32(sacc[nt], af, bf);
            }
        }

        // online softmax (rows g and g+8 of this warp's 16-row tile)
        float mx0 = -1e30f, mx1 = -1e30f;
#pragma unroll
        for (int nt = 0; nt < 8; nt++) {
            mx0 = fmaxf(mx0, fmaxf(sacc[nt][0], sacc[nt][1]));
            mx1 = fmaxf(mx1, fmaxf(sacc[nt][2], sacc[nt][3]));
        }
        mx0 = fmaxf(mx0, __shfl_xor_sync(0xffffffffu, mx0, 1));
        mx0 = fmaxf(mx0, __shfl_xor_sync(0xffffffffu, mx0, 2));
        mx1 = fmaxf(mx1, __shfl_xor_sync(0xffffffffu, mx1, 1));
        mx1 = fmaxf(mx1, __shfl_xor_sync(0xffffffffu, mx1, 2));
        const float mn0 = fmaxf(m_run0, mx0);
        const float mn1 = fmaxf(m_run1, mx1);
        const float corr0 = __expf(m_run0 - mn0);
        const float corr1 = __expf(m_run1 - mn1);
        m_run0 = mn0; m_run1 = mn1;
        float sum0 = 0.f, sum1 = 0.f;
#pragma unroll
        for (int nt = 0; nt < 8; nt++) {
            sacc[nt][0] = __expf(sacc[nt][0] - mn0);
            sacc[nt][1] = __expf(sacc[nt][1] - mn0);
            sacc[nt][2] = __expf(sacc[nt][2] - mn1);
            sacc[nt][3] = __expf(sacc[nt][3] - mn1);
            sum0 += sacc[nt][0] + sacc[nt][1];
            sum1 += sacc[nt][2] + sacc[nt][3];
        }
        sum0 += __shfl_xor_sync(0xffffffffu, sum0, 1);
        sum0 += __shfl_xor_sync(0xffffffffu, sum0, 2);
        sum1 += __shfl_xor_sync(0xffffffffu, sum1, 1);
        sum1 += __shfl_xor_sync(0xffffffffu, sum1, 2);
        l_run0 = l_run0 * corr0 + sum0;
        l_run1 = l_run1 * corr1 + sum1;
#pragma unroll
        for (int nt = 0; nt < 8; nt++) {
            oacc[nt][0] *= corr0; oacc[nt][1] *= corr0;
            oacc[nt][2] *= corr1; oacc[nt][3] *= corr1;
        }

        __syncthreads();  // all warps done reading K tile from KP
        // store P into KP (j-permuted, tf32)
#pragma unroll
        for (int nt = 0; nt < 8; nt++) {
            const int base = nt * 8;
            KP[pr0 + base + pos0]     = to_tf32(sacc[nt][0]);
            KP[pr0 + base + pos0 + 2] = to_tf32(sacc[nt][1]);
            KP[pr1 + base + pos0]     = to_tf32(sacc[nt][2]);
            KP[pr1 + base + pos0 + 2] = to_tf32(sacc[nt][3]);
        }
        __syncwarp();

        // O += P V
#pragma unroll
        for (int k0 = 0; k0 < 8; k0++) {
            float2 pA = *(const float2*)&KP[pr0 + k0 * 8 + 2 * tg];
            float2 pB = *(const float2*)&KP[pr1 + k0 * 8 + 2 * tg];
            uint32_t af[4] = {__float_as_uint(pA.x), __float_as_uint(pB.x),
                              __float_as_uint(pA.y), __float_as_uint(pB.y)};
#pragma unroll
            for (int nt = 0; nt < 8; nt++) {
                uint32_t bf[2] = {
                    __float_as_uint(Vs[(k0 * 8 + tg) * AS2 + nt * 8 + g]),
                    __float_as_uint(Vs[(k0 * 8 + tg + 4) * AS2 + nt * 8 + g])};
                mma_tf32(oacc[nt], af, bf);
            }
        }
    }

    // epilogue: normalize, transpose to [d][i] in Qs, coalesced store
    const float inv0 = 1.f / l_run0;
    const float inv1 = 1.f / l_run1;
    __syncthreads();
#pragma unroll
    for (int nt = 0; nt < 8; nt++) {
        const int d0 = nt * 8 + 2 * tg;
        Qs[d0 * AS2 + w * 16 + g]           = oacc[nt][0] * inv0;
        Qs[(d0 + 1) * AS2 + w * 16 + g]     = oacc[nt][1] * inv0;
        Qs[d0 * AS2 + w * 16 + g + 8]       = oacc[nt][2] * inv1;
        Qs[(d0 + 1) * AS2 + w * 16 + g + 8] = oacc[nt][3] * inv1;
    }
    __syncthreads();
    {
        float* dst = O + ((size_t)b * 512 + h * 64 + row) * 512 + i0 + half * 32;
        const float* src = Qs + row * AS2 + half * 32;
#pragma unroll
        for (int u = 0; u < 8; u++)
            *(float4*)&dst[u * 4] = *(const float4*)&src[u * 4];
    }
}

// ===========================================================================
extern "C" void kernel_launch(void* const* d_in, const int* in_sizes, int n_in,
                              void* d_out, int out_size) {
    (void)in_sizes; (void)n_in; (void)out_size;
    const float* query  = (const float*)d_in[0];
    const float* key    = (const float*)d_in[1];
    const float* value  = (const float*)d_in[2];
    const float* pos    = (const float*)d_in[3];
    const float* proj_w = (const float*)d_in[4];
    const float* proj_b = (const float*)d_in[5];
    const float* q_dw_w = (const float*)d_in[6];
    const float* q_dw_b = (const float*)d_in[7];
    const float* q_pw_w = (const float*)d_in[8];
    const float* q_pw_b = (const float*)d_in[9];
    const float* k_dw_w = (const float*)d_in[10];
    const float* k_dw_b = (const float*)d_in[11];
    const float* k_pw_w = (const float*)d_in[12];
    const float* k_pw_b = (const float*)d_in[13];
    const float* v_dw_w = (const float*)d_in[14];
    const float* v_dw_b = (const float*)d_in[15];
    const float* v_pw_w = (const float*)d_in[16];
    const float* v_pw_b = (const float*)d_in[17];

    float *t, *q, *k, *v, *o, *posT;
    cudaGetSymbolAddress((void**)&t, g_t);
    cudaGetSymbolAddress((void**)&q, g_q);
    cudaGetSymbolAddress((void**)&k, g_k);
    cudaGetSymbolAddress((void**)&v, g_v);
    cudaGetSymbolAddress((void**)&o, g_o);
    cudaGetSymbolAddress((void**)&posT, g_post);

    const int dsm = 32 * XST * 4;
    const int asm_sz = 3 * 64 * AS2 * 4;
    cudaFuncSetAttribute(dwconv_t_kernel,
                         cudaFuncAttributeMaxDynamicSharedMemorySize, dsm);
    cudaFuncSetAttribute(attn_mma_kernel,
                         cudaFuncAttributeMaxDynamicSharedMemorySize, asm_sz);

    transpose_pos_kernel<<<dim3(16, 16), dim3(32, 8)>>>(pos, posT);

    // q path: t in (b,l,c); Y[l][o] = sum_c t[l][c] * w[o][c]  -> q (b,l,c)
    dwconv_t_kernel<<<dim3(16, NB), 256, dsm>>>(query, posT, q_dw_w, q_dw_b, t, 1);
    gemm_mma_kernel<<<dim3(4, 4, NB), 256>>>(t, (long)LC, q_pw_w, q_pw_b, q);
    // k path
    dwconv_t_kernel<<<dim3(16, NB), 256, dsm>>>(key, posT, k_dw_w, k_dw_b, t, 1);
    gemm_mma_kernel<<<dim3(4, 4, NB), 256>>>(t, (long)LC, k_pw_w, k_pw_b, k);
    // v path
    dwconv_t_kernel<<<dim3(16, NB), 256, dsm>>>(value, posT, v_dw_w, v_dw_b, t, 0);
    gemm_mma_kernel<<<dim3(4, 4, NB), 256>>>(t, (long)LC, v_pw_w, v_pw_b, v);
    // attention (tensor cores) -> g_o in (b, c, i)
    attn_mma_kernel<<<dim3(NL / 64, NH, NB), 128, asm_sz>>>(q, k, v, o);
    // final projection: F[c][o] = sum_i O[c][i] * proj_w[o][i]
    gemm_mma_kernel<<<dim3(4, 4, NB), 256>>>(o, (long)LC, proj_w, proj_b, (float*)d_out);
}

// round 5
// speedup vs baseline: 3.2658x; 1.3005x over previous
#include <cuda_runtime.h>
#include <cstdint>

#define NB 32
#define NC 512
#define NL 512
#define NH 8
#define NDK 64
#define LC (512 * 512)

// Scratch (device globals: no allocations allowed)
__device__ float g_tq[NB * NC * NL];     // dwconv outputs, (b, l, c)
__device__ float g_tk[NB * NC * NL];
__device__ float g_tv[NB * NC * NL];
__device__ float g_q[NB * NC * NL];      // (b, l, c)
__device__ float g_k[NB * NC * NL];
__device__ float g_v[NB * NC * NL];
__device__ float g_o[NB * NC * NL];      // attention output (b, c, i)
__device__ float g_post[NC * NL];        // pos_bias transposed to (C, L)

__device__ __forceinline__ float to_tf32(float x) {
    uint32_t u;
    asm("cvt.rna.tf32.f32 %0, %1;" : "=r"(u) : "f"(x));
    return __uint_as_float(u);
}

__device__ __forceinline__ void mma_tf32(float* d, const uint32_t* a, const uint32_t* b) {
    asm volatile(
        "mma.sync.aligned.m16n8k8.row.col.f32.tf32.tf32.f32 "
        "{%0,%1,%2,%3}, {%4,%5,%6,%7}, {%8,%9}, {%0,%1,%2,%3};"
        : "+f"(d[0]), "+f"(d[1]), "+f"(d[2]), "+f"(d[3])
        : "r"(a[0]), "r"(a[1]), "r"(a[2]), "r"(a[3]), "r"(b[0]), "r"(b[1]));
}

// ===========================================================================
// pos_bias (L, C) -> posT (C, L)
// ===========================================================================
__global__ void transpose_pos_kernel(const float* __restrict__ pos,
                                     float* __restrict__ posT) {
    __shared__ float tile[32][33];
    const int c0 = blockIdx.x * 32;
    const int l0 = blockIdx.y * 32;
    const int tx = threadIdx.x;
    const int ty = threadIdx.y;
#pragma unroll
    for (int r = 0; r < 4; r++)
        tile[ty + r * 8][tx] = pos[(size_t)(l0 + ty + r * 8) * NC + c0 + tx];
    __syncthreads();
#pragma unroll
    for (int r = 0; r < 4; r++)
        posT[(size_t)(c0 + ty + r * 8) * NL + l0 + tx] = tile[tx][ty + r * 8];
}

// ===========================================================================
// Merged depthwise conv (q,k,v in one launch). Block = (c-tile 32, l-tile 128,
// z = iz*32 + b). Output y[iz][b, l, c]. pos added for iz<2 only.
// smem: 32 rows x 137 (window [l0-4, l0+132), odd stride -> conflict-free).
// ===========================================================================
#define DST 137
__global__ __launch_bounds__(256) void dwconv_merged_kernel(
    const float* x0, const float* x1, const float* x2,
    const float* __restrict__ posT,
    const float* w0, const float* w1, const float* w2,
    const float* b0, const float* b1, const float* b2,
    float* y0, float* y1, float* y2) {
    __shared__ float sx[32 * DST];
    const int tid = threadIdx.x;
    const int c0 = blockIdx.x * 32;
    const int l0 = blockIdx.y * 128;
    const int iz = blockIdx.z >> 5;
    const int b = blockIdx.z & 31;
    const float* xin[3] = {x0, x1, x2};
    const float* win3[3] = {w0, w1, w2};
    const float* bin[3] = {b0, b1, b2};
    float* yout[3] = {y0, y1, y2};
    const float* x = xin[iz];
    const float* w = win3[iz];
    const float* bias = bin[iz];
    float* y = yout[iz];
    const int add_pos = (iz < 2);

    // load phase: 32 rows x 34 float4 covering l in [l0-4, l0+132)
    {
        const int lr = tid >> 3;
        const int tj = tid & 7;
        const float* xrow = x + ((size_t)b * NC + c0 + lr) * NL;
        const float* prow = posT + (size_t)(c0 + lr) * NL;
        float* sd = &sx[lr * DST];
#pragma unroll
        for (int jj = 0; jj < 5; jj++) {
            const int j = tj + jj * 8;
            if (j < 34) {
                const int l = l0 - 4 + 4 * j;
                float4 v = {0.f, 0.f, 0.f, 0.f};
                if (l >= 0 && l <= 508) {
                    v = *(const float4*)&xrow[l];
                    if (add_pos) {
                        float4 p = *(const float4*)&prow[l];
                        v.x += p.x; v.y += p.y; v.z += p.z; v.w += p.w;
                    }
                }
                sd[4 * j + 0] = v.x; sd[4 * j + 1] = v.y;
                sd[4 * j + 2] = v.z; sd[4 * j + 3] = v.w;
            }
        }
    }
    __syncthreads();

    // compute: thread = (channel cc, 16 consecutive l)
    const int cc = tid & 31;
    const int o0 = (tid >> 5) * 16;
    float wt[7];
#pragma unroll
    for (int t = 0; t < 7; t++) wt[t] = w[(c0 + cc) * 7 + t];
    const float bs = bias[c0 + cc];
    const float* xr = &sx[cc * DST];
    float winv[7];
#pragma unroll
    for (int t = 0; t < 6; t++) winv[t] = xr[o0 + 1 + t];
    float* yb = y + (size_t)b * LC + c0 + cc;
#pragma unroll
    for (int r = 0; r < 16; r++) {
        winv[6] = xr[o0 + r + 7];
        float acc = bs;
#pragma unroll
        for (int t = 0; t < 7; t++) acc += winv[t] * wt[t];
        yb[(size_t)(l0 + o0 + r) * NC] = acc;
#pragma unroll
        for (int t = 0; t < 6; t++) winv[t] = winv[t + 1];
    }
}

// ===========================================================================
// Batched GEMM (tf32 mma): Y[g][zb][m][n] = sum_k A[g][zb][m][k]*W[g][n][k]+b[g][n]
// grp = blockIdx.z>>5, zb = blockIdx.z&31. CTA 128x128, BK=16, double-buffered,
// 256 thr (8 warps 2m x 4n), unpermuted smem.
// ===========================================================================
#define PK 20
__global__ __launch_bounds__(256) void gemm_mma_kernel(
    const float* A0, const float* A1, const float* A2,
    const float* W0, const float* W1, const float* W2,
    const float* bi0, const float* bi1, const float* bi2,
    float* Y0, float* Y1, float* Y2) {
    __shared__ float As[2][128 * PK];
    __shared__ float Bs[2][128 * PK];

    const int tid = threadIdx.x;
    const int lane = tid & 31;
    const int g = lane >> 2;
    const int tg = lane & 3;
    const int wm = (tid >> 5) >> 2;
    const int wn = (tid >> 5) & 3;
    const int n0 = blockIdx.x * 128;
    const int m0 = blockIdx.y * 128;
    const int grp = blockIdx.z >> 5;
    const int zb = blockIdx.z & 31;
    const float* Aarr[3] = {A0, A1, A2};
    const float* Warr[3] = {W0, W1, W2};
    const float* barr[3] = {bi0, bi1, bi2};
    float* Yarr[3] = {Y0, Y1, Y2};
    const float* Ab = Aarr[grp] + (size_t)zb * LC;
    const float* W = Warr[grp];
    const float* bias = barr[grp];
    float* Yb = Yarr[grp] + (size_t)zb * LC;

    const int lrow = tid >> 1;
    const int lhalf = tid & 1;
    const float* Arow = Ab + (size_t)(m0 + lrow) * 512 + lhalf * 8;
    const float* Brow = W + (size_t)(n0 + lrow) * 512 + lhalf * 8;
    const int soff = lrow * PK + lhalf * 8;

    float acc[4][4][4];
#pragma unroll
    for (int mi = 0; mi < 4; mi++)
#pragma unroll
        for (int ni = 0; ni < 4; ni++)
#pragma unroll
            for (int r = 0; r < 4; r++) acc[mi][ni][r] = 0.f;

    float4 a0r = *(const float4*)&Arow[0];
    float4 a1r = *(const float4*)&Arow[4];
    float4 b0r = *(const float4*)&Brow[0];
    float4 b1r = *(const float4*)&Brow[4];
    {
        float4 t0 = {to_tf32(a0r.x), to_tf32(a0r.y), to_tf32(a0r.z), to_tf32(a0r.w)};
        float4 t1 = {to_tf32(a1r.x), to_tf32(a1r.y), to_tf32(a1r.z), to_tf32(a1r.w)};
        float4 t2 = {to_tf32(b0r.x), to_tf32(b0r.y), to_tf32(b0r.z), to_tf32(b0r.w)};
        float4 t3 = {to_tf32(b1r.x), to_tf32(b1r.y), to_tf32(b1r.z), to_tf32(b1r.w)};
        *(float4*)&As[0][soff] = t0; *(float4*)&As[0][soff + 4] = t1;
        *(float4*)&Bs[0][soff] = t2; *(float4*)&Bs[0][soff + 4] = t3;
    }
    __syncthreads();

    for (int kc = 0; kc < 32; kc++) {
        const int cur = kc & 1;
        if (kc < 31) {
            const int k0n = (kc + 1) * 16;
            a0r = *(const float4*)&Arow[k0n];
            a1r = *(const float4*)&Arow[k0n + 4];
            b0r = *(const float4*)&Brow[k0n];
            b1r = *(const float4*)&Brow[k0n + 4];
        }
#pragma unroll
        for (int s = 0; s < 2; s++) {
            uint32_t af[4][4];
#pragma unroll
            for (int mi = 0; mi < 4; mi++) {
                const float* p = &As[cur][(wm * 64 + mi * 16 + g) * PK + s * 8 + tg];
                af[mi][0] = __float_as_uint(p[0]);
                af[mi][1] = __float_as_uint(p[8 * PK]);
                af[mi][2] = __float_as_uint(p[4]);
                af[mi][3] = __float_as_uint(p[8 * PK + 4]);
            }
            uint32_t bf[4][2];
#pragma unroll
            for (int ni = 0; ni < 4; ni++) {
                const float* q = &Bs[cur][(wn * 32 + ni * 8 + g) * PK + s * 8 + tg];
                bf[ni][0] = __float_as_uint(q[0]);
                bf[ni][1] = __float_as_uint(q[4]);
            }
#pragma unroll
            for (int mi = 0; mi < 4; mi++)
#pragma unroll
                for (int ni = 0; ni < 4; ni++)
                    mma_tf32(acc[mi][ni], af[mi], bf[ni]);
        }
        if (kc < 31) {
            const int nxt = cur ^ 1;
            float4 t0 = {to_tf32(a0r.x), to_tf32(a0r.y), to_tf32(a0r.z), to_tf32(a0r.w)};
            float4 t1 = {to_tf32(a1r.x), to_tf32(a1r.y), to_tf32(a1r.z), to_tf32(a1r.w)};
            float4 t2 = {to_tf32(b0r.x), to_tf32(b0r.y), to_tf32(b0r.z), to_tf32(b0r.w)};
            float4 t3 = {to_tf32(b1r.x), to_tf32(b1r.y), to_tf32(b1r.z), to_tf32(b1r.w)};
            *(float4*)&As[nxt][soff] = t0; *(float4*)&As[nxt][soff + 4] = t1;
            *(float4*)&Bs[nxt][soff] = t2; *(float4*)&Bs[nxt][soff + 4] = t3;
        }
        __syncthreads();
    }

#pragma unroll
    for (int mi = 0; mi < 4; mi++) {
        const int m = m0 + wm * 64 + mi * 16 + g;
#pragma unroll
        for (int ni = 0; ni < 4; ni++) {
            const int n = n0 + wn * 32 + ni * 8 + 2 * tg;
            const float bn0 = bias[n], bn1 = bias[n + 1];
            float2 o0 = {acc[mi][ni][0] + bn0, acc[mi][ni][1] + bn1};
            float2 o1 = {acc[mi][ni][2] + bn0, acc[mi][ni][3] + bn1};
            *(float2*)&Yb[(size_t)m * 512 + n] = o0;
            *(float2*)&Yb[(size_t)(m + 8) * 512 + n] = o1;
        }
    }
}

// ===========================================================================
// Flash attention (tf32 mma), 128-i CTA: 256 thr = 8 warps, two 64-i groups
// sharing K/V staging. Inputs (b,l,c), output (b,c,i).
// smem: Qs[128][68] | KP[128][68] (K rows 0..63, then P rows 0..127) | Vs[64][68]
// ===========================================================================
#define AS2 68
__global__ __launch_bounds__(256) void attn_mma_kernel(
    const float* __restrict__ Q, const float* __restrict__ K,
    const float* __restrict__ V, float* __restrict__ O) {
    extern __shared__ float sm[];
    float* Qs = sm;                  // [128][AS2]
    float* KP = sm + 128 * AS2;      // [128][AS2]
    float* Vs = sm + 256 * AS2;      // [64][AS2]

    const int tid = threadIdx.x;
    const int w = tid >> 5;
    const int lane = tid & 31;
    const int g = lane >> 2;
    const int tg = lane & 3;
    const int it = w >> 2;           // which 64-i group
    const int wq = w & 3;            // warp within group
    const int b = blockIdx.z;
    const int h = blockIdx.y;
    const int i0 = blockIdx.x * 128;

    const float* Qb = Q + (size_t)b * LC + h * 64;
    const float* Kb = K + (size_t)b * LC + h * 64;
    const float* Vb = V + (size_t)b * LC + h * 64;

    // Q load: 128 rows, d-permuted, scaled, tf32
    {
        const int row = tid >> 1;
        const int half = tid & 1;
        const float* src = Qb + (size_t)(i0 + row) * 512 + half * 32;
        float* dst = Qs + row * AS2 + half * 32;
#pragma unroll
        for (int u = 0; u < 8; u++) {
            float4 x = *(const float4*)&src[u * 4];
            float* d8 = dst + (u >> 1) * 8 + (u & 1);
            d8[0] = to_tf32(x.x * 0.125f);
            d8[2] = to_tf32(x.y * 0.125f);
            d8[4] = to_tf32(x.z * 0.125f);
            d8[6] = to_tf32(x.w * 0.125f);
        }
    }

    float m_run0 = -1e30f, m_run1 = -1e30f, l_run0 = 0.f, l_run1 = 0.f;
    float oacc[8][4];
#pragma unroll
    for (int nt = 0; nt < 8; nt++)
#pragma unroll
        for (int r = 0; r < 4; r++) oacc[nt][r] = 0.f;

    const int pr0 = (it * 64 + wq * 16 + g) * AS2;
    const int pr1 = pr0 + 8 * AS2;
    const int pos0 = ((2 * tg) & 3) * 2 + ((2 * tg) >> 2);

    const int krow = tid >> 2;       // 0..63
    const int kq = tid & 3;          // 16-float quarter

    for (int jt = 0; jt < 8; jt++) {
        const int j0 = jt * 64;
        __syncthreads();  // prev PV done / Q ready
        {
            const float* ks = Kb + (size_t)(j0 + krow) * 512 + kq * 16;
            float* kd = KP + krow * AS2 + kq * 16;
            const float* vsrc = Vb + (size_t)(j0 + krow) * 512 + kq * 16;
            float* vd = Vs + krow * AS2 + kq * 16;
#pragma unroll
            for (int u = 0; u < 4; u++) {
                float4 x = *(const float4*)&ks[u * 4];
                float* d8 = kd + (u >> 1) * 8 + (u & 1);
                d8[0] = to_tf32(x.x); d8[2] = to_tf32(x.y);
                d8[4] = to_tf32(x.z); d8[6] = to_tf32(x.w);
                float4 y = *(const float4*)&vsrc[u * 4];
                float4 t = {to_tf32(y.x), to_tf32(y.y), to_tf32(y.z), to_tf32(y.w)};
                *(float4*)&vd[u * 4] = t;
            }
        }
        __syncthreads();

        // S = Q K^T
        float sacc[8][4];
#pragma unroll
        for (int nt = 0; nt < 8; nt++)
#pragma unroll
            for (int r = 0; r < 4; r++) sacc[nt][r] = 0.f;
#pragma unroll
        for (int k0 = 0; k0 < 8; k0++) {
            float2 aA = *(const float2*)&Qs[pr0 + k0 * 8 + 2 * tg];
            float2 aB = *(const float2*)&Qs[pr1 + k0 * 8 + 2 * tg];
            uint32_t af[4] = {__float_as_uint(aA.x), __float_as_uint(aB.x),
                              __float_as_uint(aA.y), __float_as_uint(aB.y)};
#pragma unroll
            for (int nt = 0; nt < 8; nt++) {
                float2 bb = *(const float2*)&KP[(nt * 8 + g) * AS2 + k0 * 8 + 2 * tg];
                uint32_t bf[2] = {__float_as_uint(bb.x), __float_as_uint(bb.y)};
                mma_tf32(sacc[nt], af, bf);
            }
        }

        // online softmax
        float mx0 = -1e30f, mx1 = -1e30f;
#pragma unroll
        for (int nt = 0; nt < 8; nt++) {
            mx0 = fmaxf(mx0, fmaxf(sacc[nt][0], sacc[nt][1]));
            mx1 = fmaxf(mx1, fmaxf(sacc[nt][2], sacc[nt][3]));
        }
        mx0 = fmaxf(mx0, __shfl_xor_sync(0xffffffffu, mx0, 1));
        mx0 = fmaxf(mx0, __shfl_xor_sync(0xffffffffu, mx0, 2));
        mx1 = fmaxf(mx1, __shfl_xor_sync(0xffffffffu, mx1, 1));
        mx1 = fmaxf(mx1, __shfl_xor_sync(0xffffffffu, mx1, 2));
        const float mn0 = fmaxf(m_run0, mx0);
        const float mn1 = fmaxf(m_run1, mx1);
        const float corr0 = __expf(m_run0 - mn0);
        const float corr1 = __expf(m_run1 - mn1);
        m_run0 = mn0; m_run1 = mn1;
        float sum0 = 0.f, sum1 = 0.f;
#pragma unroll
        for (int nt = 0; nt < 8; nt++) {
            sacc[nt][0] = __expf(sacc[nt][0] - mn0);
            sacc[nt][1] = __expf(sacc[nt][1] - mn0);
            sacc[nt][2] = __expf(sacc[nt][2] - mn1);
            sacc[nt][3] = __expf(sacc[nt][3] - mn1);
            sum0 += sacc[nt][0] + sacc[nt][1];
            sum1 += sacc[nt][2] + sacc[nt][3];
        }
        sum0 += __shfl_xor_sync(0xffffffffu, sum0, 1);
        sum0 += __shfl_xor_sync(0xffffffffu, sum0, 2);
        sum1 += __shfl_xor_sync(0xffffffffu, sum1, 1);
        sum1 += __shfl_xor_sync(0xffffffffu, sum1, 2);
        l_run0 = l_run0 * corr0 + sum0;
        l_run1 = l_run1 * corr1 + sum1;
#pragma unroll
        for (int nt = 0; nt < 8; nt++) {
            oacc[nt][0] *= corr0; oacc[nt][1] *= corr0;
            oacc[nt][2] *= corr1; oacc[nt][3] *= corr1;
        }

        __syncthreads();  // all warps done reading K rows of KP
#pragma unroll
        for (int nt = 0; nt < 8; nt++) {
            const int base = nt * 8;
            KP[pr0 + base + pos0]     = to_tf32(sacc[nt][0]);
            KP[pr0 + base + pos0 + 2] = to_tf32(sacc[nt][1]);
            KP[pr1 + base + pos0]     = to_tf32(sacc[nt][2]);
            KP[pr1 + base + pos0 + 2] = to_tf32(sacc[nt][3]);
        }
        __syncwarp();

        // O += P V
#pragma unroll
        for (int k0 = 0; k0 < 8; k0++) {
            float2 pA = *(const float2*)&KP[pr0 + k0 * 8 + 2 * tg];
            float2 pB = *(const float2*)&KP[pr1 + k0 * 8 + 2 * tg];
            uint32_t af[4] = {__float_as_uint(pA.x), __float_as_uint(pB.x),
                              __float_as_uint(pA.y), __float_as_uint(pB.y)};
#pragma unroll
            for (int nt = 0; nt < 8; nt++) {
                uint32_t bf[2] = {
                    __float_as_uint(Vs[(k0 * 8 + tg) * AS2 + nt * 8 + g]),
                    __float_as_uint(Vs[(k0 * 8 + tg + 4) * AS2 + nt * 8 + g])};
                mma_tf32(oacc[nt], af, bf);
            }
        }
    }

    // epilogue: normalize, stage [d][i] per it-group in Qs, coalesced store
    const float inv0 = 1.f / l_run0;
    const float inv1 = 1.f / l_run1;
    __syncthreads();
#pragma unroll
    for (int nt = 0; nt < 8; nt++) {
        const int d0 = nt * 8 + 2 * tg;
        Qs[(it * 64 + d0) * AS2 + wq * 16 + g]           = oacc[nt][0] * inv0;
        Qs[(it * 64 + d0 + 1) * AS2 + wq * 16 + g]       = oacc[nt][1] * inv0;
        Qs[(it * 64 + d0) * AS2 + wq * 16 + g + 8]       = oacc[nt][2] * inv1;
        Qs[(it * 64 + d0 + 1) * AS2 + wq * 16 + g + 8]   = oacc[nt][3] * inv1;
    }
    __syncthreads();
    {
        const int r = tid >> 1;          // 0..127: itr = r>>6, d = r&63
        const int half = tid & 1;
        const int itr = r >> 6;
        const int d = r & 63;
        float* dst = O + ((size_t)b * 512 + h * 64 + d) * 512 + i0 + itr * 64 + half * 32;
        const float* src = Qs + r * AS2 + half * 32;
#pragma unroll
        for (int u = 0; u < 8; u++)
            *(float4*)&dst[u * 4] = *(const float4*)&src[u * 4];
    }
}

// ===========================================================================
extern "C" void kernel_launch(void* const* d_in, const int* in_sizes, int n_in,
                              void* d_out, int out_size) {
    (void)in_sizes; (void)n_in; (void)out_size;
    const float* query  = (const float*)d_in[0];
    const float* key    = (const float*)d_in[1];
    const float* value  = (const float*)d_in[2];
    const float* pos    = (const float*)d_in[3];
    const float* proj_w = (const float*)d_in[4];
    const float* proj_b = (const float*)d_in[5];
    const float* q_dw_w = (const float*)d_in[6];
    const float* q_dw_b = (const float*)d_in[7];
    const float* q_pw_w = (const float*)d_in[8];
    const float* q_pw_b = (const float*)d_in[9];
    const float* k_dw_w = (const float*)d_in[10];
    const float* k_dw_b = (const float*)d_in[11];
    const float* k_pw_w = (const float*)d_in[12];
    const float* k_pw_b = (const float*)d_in[13];
    const float* v_dw_w = (const float*)d_in[14];
    const float* v_dw_b = (const float*)d_in[15];
    const float* v_pw_w = (const float*)d_in[16];
    const float* v_pw_b = (const float*)d_in[17];

    float *tq, *tk, *tv, *q, *k, *v, *o, *posT;
    cudaGetSymbolAddress((void**)&tq, g_tq);
    cudaGetSymbolAddress((void**)&tk, g_tk);
    cudaGetSymbolAddress((void**)&tv, g_tv);
    cudaGetSymbolAddress((void**)&q, g_q);
    cudaGetSymbolAddress((void**)&k, g_k);
    cudaGetSymbolAddress((void**)&v, g_v);
    cudaGetSymbolAddress((void**)&o, g_o);
    cudaGetSymbolAddress((void**)&posT, g_post);

    const int attn_smem = 320 * AS2 * 4;  // 87040
    cudaFuncSetAttribute(attn_mma_kernel,
                         cudaFuncAttributeMaxDynamicSharedMemorySize, attn_smem);

    transpose_pos_kernel<<<dim3(16, 16), dim3(32, 8)>>>(pos, posT);

    // merged q/k/v depthwise conv
    dwconv_merged_kernel<<<dim3(16, 4, 96), 256>>>(
        query, key, value, posT,
        q_dw_w, k_dw_w, v_dw_w,
        q_dw_b, k_dw_b, v_dw_b,
        tq, tk, tv);

    // merged q/k/v pointwise GEMMs
    gemm_mma_kernel<<<dim3(4, 4, 96), 256>>>(
        tq, tk, tv,
        q_pw_w, k_pw_w, v_pw_w,
        q_pw_b, k_pw_b, v_pw_b,
        q, k, v);

    // attention -> g_o (b, c, i)
    attn_mma_kernel<<<dim3(NL / 128, NH, NB), 256, attn_smem>>>(q, k, v, o);

    // final projection: F[c][o] = sum_i O[c][i] * proj_w[o][i]
    gemm_mma_kernel<<<dim3(4, 4, 32), 256>>>(
        o, o, o, proj_w, proj_w, proj_w, proj_b, proj_b, proj_b,
        (float*)d_out, (float*)d_out, (float*)d_out);
}